// round 15
// baseline (speedup 1.0000x reference)
#include <cuda_runtime.h>
#include <cuda_fp16.h>
#include <math.h>
#include <stdint.h>

static const int NN  = 4096;
static const int NE  = 131072;
static const int DD  = 256;
static const int DIN = 16;
static const int D2  = 512;
static const int D3  = 768;
static const int YCOFF = NN * D2;   // offset of Yc inside g_Ya

// ---------------- device scratch ----------------
__device__ float g_xacc[NN * DD];
__device__ float g_S[NN * 17];
__device__ float g_cat[NN * D3];          // [xout | hglob | h0]
__device__ float g_Ya[2 * NN * D2];       // [Ya | Yc]
__device__ float g_Meb[DIN * D2];
__device__ float g_bb1[D2];
__device__ float g_w2p[16 * 64 * 32 * 4]; // fragment-packed w2 (fp16 m16n8k16 frags)
__device__ float g_w3p[16 * 32 * 4];      // fragment-packed w3 (fp16 A-frags, M=16)
__device__ float g_qkv[NN * D3];
__device__ __half g_qkvh[NN * D3];        // fp16 copy for flash staging
__device__ float g_attnO[NN * DD];
__device__ float g_tmp[NN * DD];
__device__ int   g_is64;

__device__ __forceinline__ float gelu_f(float x) {
    return 0.5f * x * (1.f + erff(x * 0.70710678118654752f));
}

__device__ __forceinline__ unsigned tf32r(float x) {
    unsigned u;
    asm("cvt.rna.tf32.f32 %0, %1;" : "=r"(u) : "f"(x));
    return u;
}
__device__ __forceinline__ float tf32f(float x) {
    return __uint_as_float(tf32r(x));
}

__device__ __forceinline__ unsigned h2pack(float x, float y) {
    __half2 h = __floats2half2_rn(x, y);
    return *(unsigned*)&h;
}

// m16n8k8 tf32 mma
__device__ __forceinline__ void mma_tf32(
    float& c0, float& c1, float& c2, float& c3,
    unsigned a0, unsigned a1, unsigned a2, unsigned a3,
    unsigned b0, unsigned b1) {
    asm("mma.sync.aligned.m16n8k8.row.col.f32.tf32.tf32.f32 "
        "{%0,%1,%2,%3}, {%4,%5,%6,%7}, {%8,%9}, {%0,%1,%2,%3};"
        : "+f"(c0), "+f"(c1), "+f"(c2), "+f"(c3)
        : "r"(a0), "r"(a1), "r"(a2), "r"(a3), "r"(b0), "r"(b1));
}

// m16n8k16 fp16 mma (fp32 accum)
__device__ __forceinline__ void mma_f16(
    float& c0, float& c1, float& c2, float& c3,
    unsigned a0, unsigned a1, unsigned a2, unsigned a3,
    unsigned b0, unsigned b1) {
    asm("mma.sync.aligned.m16n8k16.row.col.f32.f16.f16.f32 "
        "{%0,%1,%2,%3}, {%4,%5,%6,%7}, {%8,%9}, {%0,%1,%2,%3};"
        : "+f"(c0), "+f"(c1), "+f"(c2), "+f"(c3)
        : "r"(a0), "r"(a1), "r"(a2), "r"(a3), "r"(b0), "r"(b1));
}

__device__ __forceinline__ void ldmx4(unsigned& r0, unsigned& r1, unsigned& r2, unsigned& r3,
                                      unsigned addr) {
    asm volatile("ldmatrix.sync.aligned.m8n8.x4.shared.b16 {%0,%1,%2,%3}, [%4];"
                 : "=r"(r0), "=r"(r1), "=r"(r2), "=r"(r3) : "r"(addr));
}
__device__ __forceinline__ void ldmx4t(unsigned& r0, unsigned& r1, unsigned& r2, unsigned& r3,
                                       unsigned addr) {
    asm volatile("ldmatrix.sync.aligned.m8n8.x4.trans.shared.b16 {%0,%1,%2,%3}, [%4];"
                 : "=r"(r0), "=r"(r1), "=r"(r2), "=r"(r3) : "r"(addr));
}

__device__ __forceinline__ void cpasync16(unsigned saddr, const void* g) {
    asm volatile("cp.async.cg.shared.global [%0], [%1], 16;" :: "r"(saddr), "l"(g));
}
__device__ __forceinline__ void cpcommit() {
    asm volatile("cp.async.commit_group;");
}
__device__ __forceinline__ void cpwait0() {
    asm volatile("cp.async.wait_group 0;");
}

// fast exp (FFMA-only 2^x poly)
__device__ __forceinline__ float fexp(float x) {
    float t = fmaxf(x * 1.442695041f, -126.f);
    float fi = floorf(t);
    float f = t - fi;
    float p = 1.33336e-3f;
    p = fmaf(p, f, 9.61813e-3f);
    p = fmaf(p, f, 5.55041e-2f);
    p = fmaf(p, f, 2.40226e-1f);
    p = fmaf(p, f, 6.93147e-1f);
    p = fmaf(p, f, 1.0f);
    return p * __int_as_float(((int)fi + 127) << 23);
}

// vector reduction atomic (sm_90+)
__device__ __forceinline__ void red4(float* p, float a, float b, float c, float d) {
    asm volatile("red.global.add.v4.f32 [%0], {%1,%2,%3,%4};"
                 :: "l"(p), "f"(a), "f"(b), "f"(c), "f"(d) : "memory");
}

// ---------------- adj dtype detection ----------------
__global__ void k_detect(const void* __restrict__ adj) {
    if (threadIdx.x == 0) {
        const long long* a = (const long long*)adj;
        int ok = 1;
        for (int e = 0; e < 64; e++) {
            long long v = a[e];
            if (v < 0 || v >= NN) ok = 0;
        }
        g_is64 = ok;
    }
}
__device__ __forceinline__ int edge_idx(const void* adj, int i) {
    if (g_is64) return (int)((const long long*)adj)[i];
    return ((const int*)adj)[i];
}

// ---------------- init: xacc=input, S=0, cat[:,512:768]=h0 ----------------
__global__ void k_init(const float* __restrict__ input,
                       const float* __restrict__ h0) {
    int i = blockIdx.x * 256 + threadIdx.x;
    const int NM = NN * DD;
    const int NS = NN * 17;
    if (i < NM) g_xacc[i] = input[i];
    else if (i < NM + NS) g_S[i - NM] = 0.f;
    else if (i < 2 * NM + NS) {
        int j = i - NM - NS;
        g_cat[(size_t)(j >> 8) * D3 + 512 + (j & 255)] = h0[j];
    }
}

// ---------------- qkv -> fp16 ----------------
__global__ void k_qkvh() {
    int i = blockIdx.x * 256 + threadIdx.x;
    float4 v = ((const float4*)g_qkv)[i];
    uint2 o;
    o.x = h2pack(v.x, v.y);
    o.y = h2pack(v.z, v.w);
    ((uint2*)g_qkvh)[i] = o;
}

// ---------------- scatter ----------------
__global__ void k_scatter(const void* __restrict__ adj,
                          const float* __restrict__ x,
                          const float* __restrict__ dmv,
                          const float* __restrict__ norm) {
    int e = blockIdx.x * 8 + (threadIdx.x >> 5);
    int lane = threadIdx.x & 31;
    int src = edge_idx(adj, e);
    int dst = edge_idx(adj, NE + e);
    float nrm = norm[e];
    const float4* xr = (const float4*)(x + (size_t)src * DD);
    float* out = g_xacc + (size_t)dst * DD;
#pragma unroll
    for (int t = 0; t < 2; t++) {
        float4 v = xr[lane + t * 32];
        int c = (lane + t * 32) * 4;
        red4(out + c, nrm * v.x, nrm * v.y, nrm * v.z, nrm * v.w);
    }
    if (lane < DIN)       atomicAdd(&g_S[dst * 17 + lane], nrm * dmv[(size_t)e * DIN + lane]);
    else if (lane == DIN) atomicAdd(&g_S[dst * 17 + 16], nrm);
}

// ---------------- x_out -> g_cat[:,0:256] ----------------
__global__ void k_finalize_xout(const float* __restrict__ lin_w,
                                const float* __restrict__ lin_b) {
    int i = blockIdx.x * 256 + threadIdx.x;
    int n = i >> 8, d = i & 255;
    const float* Sr = g_S + n * 17;
    float v = g_xacc[i];
#pragma unroll
    for (int k = 0; k < 16; k++) v += Sr[k] * lin_w[d * 16 + k];
    v += Sr[16] * lin_b[d];
    g_cat[(size_t)n * D3 + d] = v;
}

// ---------------- precompute Meb, bb1 ----------------
__global__ void k_meb(const float* __restrict__ lin_w, const float* __restrict__ lin_b,
                      const float* __restrict__ w1, const float* __restrict__ b1) {
    int k = blockIdx.x;
    for (int j = threadIdx.x; j < D2; j += 256) {
        const float* wr = w1 + (size_t)j * D3 + DD;
        float acc = 0.f;
        for (int d = 0; d < DD; d++) acc += lin_w[d * 16 + k] * wr[d];
        g_Meb[k * D2 + j] = acc;
        if (k == 0) {
            float lb = 0.f;
            for (int d = 0; d < DD; d++) lb += lin_b[d] * wr[d];
            g_bb1[j] = b1[j] + lb;
        }
    }
}

// ---------------- pack w2/w3 into fp16 m16n8k16 A-fragments ----------------
__global__ void k_w2pack(const float* __restrict__ w2, const float* __restrict__ w3) {
    int t = blockIdx.x * 256 + threadIdx.x;  // 16384 + 512
    int lane = t & 31;
    int gid = lane >> 2, ctid = lane & 3;
    if (t < 16384) {
        int KS = (t >> 5) & 31;
        int MT = t >> 10;
        int r0 = MT * 16 + gid, c0 = KS * 16 + 2 * ctid;
        uint4 v;
        v.x = h2pack(w2[(size_t)r0 * D2 + c0],       w2[(size_t)r0 * D2 + c0 + 1]);
        v.y = h2pack(w2[(size_t)(r0 + 8) * D2 + c0], w2[(size_t)(r0 + 8) * D2 + c0 + 1]);
        v.z = h2pack(w2[(size_t)r0 * D2 + c0 + 8],   w2[(size_t)r0 * D2 + c0 + 9]);
        v.w = h2pack(w2[(size_t)(r0 + 8) * D2 + c0 + 8], w2[(size_t)(r0 + 8) * D2 + c0 + 9]);
        ((uint4*)g_w2p)[t] = v;
    } else {
        int u = t - 16384;          // 0..511
        int KS = u >> 5;            // 0..15
        int r0 = gid, c0 = KS * 16 + 2 * ctid;
        uint4 v;
        v.x = h2pack(w3[(size_t)r0 * DD + c0],       w3[(size_t)r0 * DD + c0 + 1]);
        v.y = h2pack(w3[(size_t)(r0 + 8) * DD + c0], w3[(size_t)(r0 + 8) * DD + c0 + 1]);
        v.z = h2pack(w3[(size_t)r0 * DD + c0 + 8],   w3[(size_t)r0 * DD + c0 + 9]);
        v.w = h2pack(w3[(size_t)(r0 + 8) * DD + c0 + 8], w3[(size_t)(r0 + 8) * DD + c0 + 9]);
        ((uint4*)g_w3p)[u] = v;
    }
}

// ---------------- tf32 tensor-core GEMM: 128x128 tile ----------------
__global__ __launch_bounds__(256) void gemm_tc(
    const float* __restrict__ A, int lda,
    const float* __restrict__ B, int ldb,
    float* __restrict__ C, int ldc,
    int K, float alpha, const float* __restrict__ bias,
    int accum, int transB, int atomic, int zbo, long zco) {
    __shared__ float As[128 * 36];
    __shared__ float Bs[128 * 36];
    int tid = threadIdx.x, lane = tid & 31, warp = tid >> 5;
    int gid = lane >> 2, ctid = lane & 3;
    int m0 = blockIdx.y << 7, j0 = blockIdx.x << 7;
    int kbase;
    if (zco != 0) {
        B += (size_t)blockIdx.z * zbo;
        C += (size_t)blockIdx.z * zco;
        kbase = 0;
    } else {
        kbase = blockIdx.z * K;
    }
    int wm = (warp >> 2) << 6;
    int wn = (warp & 3) << 5;
    int arow = tid >> 1, acol = (tid & 1) << 4;
    float acc[4][4][4];
#pragma unroll
    for (int a = 0; a < 4; a++)
#pragma unroll
        for (int b = 0; b < 4; b++)
#pragma unroll
            for (int c = 0; c < 4; c++) acc[a][b][c] = 0.f;

    for (int k0 = kbase; k0 < kbase + K; k0 += 32) {
        __syncthreads();
        {
            const float* ap = A + (size_t)(m0 + arow) * lda + k0 + acol;
            float* asp = As + arow * 36 + acol;
#pragma unroll
            for (int i = 0; i < 4; i++) {
                float4 v = *(const float4*)(ap + 4 * i);
                asp[4 * i + 0] = tf32f(v.x);
                asp[4 * i + 1] = tf32f(v.y);
                asp[4 * i + 2] = tf32f(v.z);
                asp[4 * i + 3] = tf32f(v.w);
            }
        }
        if (transB) {
            const float* bp = B + (size_t)(j0 + arow) * ldb + k0 + acol;
            float* bsp = Bs + arow * 36 + acol;
#pragma unroll
            for (int i = 0; i < 4; i++) {
                float4 v = *(const float4*)(bp + 4 * i);
                bsp[4 * i + 0] = tf32f(v.x);
                bsp[4 * i + 1] = tf32f(v.y);
                bsp[4 * i + 2] = tf32f(v.z);
                bsp[4 * i + 3] = tf32f(v.w);
            }
        } else {
            int kr = tid >> 3, nc = (tid & 7) << 4;
            const float* bp = B + (size_t)(k0 + kr) * ldb + j0 + nc;
#pragma unroll
            for (int i = 0; i < 4; i++) {
                float4 v = *(const float4*)(bp + 4 * i);
                Bs[(nc + 4 * i + 0) * 36 + kr] = tf32f(v.x);
                Bs[(nc + 4 * i + 1) * 36 + kr] = tf32f(v.y);
                Bs[(nc + 4 * i + 2) * 36 + kr] = tf32f(v.z);
                Bs[(nc + 4 * i + 3) * 36 + kr] = tf32f(v.w);
            }
        }
        __syncthreads();
#pragma unroll
        for (int ks = 0; ks < 4; ks++) {
            int kk = ks << 3;
            unsigned a[4][4], b[4][2];
#pragma unroll
            for (int mt = 0; mt < 4; mt++) {
                const float* p = As + (wm + mt * 16 + gid) * 36 + kk + ctid;
                a[mt][0] = __float_as_uint(p[0]);
                a[mt][1] = __float_as_uint(p[8 * 36]);
                a[mt][2] = __float_as_uint(p[4]);
                a[mt][3] = __float_as_uint(p[8 * 36 + 4]);
            }
#pragma unroll
            for (int nt = 0; nt < 4; nt++) {
                const float* q = Bs + (wn + nt * 8 + gid) * 36 + kk + ctid;
                b[nt][0] = __float_as_uint(q[0]);
                b[nt][1] = __float_as_uint(q[4]);
            }
#pragma unroll
            for (int mt = 0; mt < 4; mt++)
#pragma unroll
                for (int nt = 0; nt < 4; nt++)
                    mma_tf32(acc[mt][nt][0], acc[mt][nt][1], acc[mt][nt][2], acc[mt][nt][3],
                             a[mt][0], a[mt][1], a[mt][2], a[mt][3],
                             b[nt][0], b[nt][1]);
        }
    }
#pragma unroll
    for (int mt = 0; mt < 4; mt++) {
#pragma unroll
        for (int nt = 0; nt < 4; nt++) {
            int r0 = m0 + wm + mt * 16 + gid;
            int c = j0 + wn + nt * 8 + 2 * ctid;
            float v0 = alpha * acc[mt][nt][0], v1 = alpha * acc[mt][nt][1];
            float v2 = alpha * acc[mt][nt][2], v3 = alpha * acc[mt][nt][3];
            if (bias) {
                float b0 = bias[c], b1 = bias[c + 1];
                v0 += b0; v1 += b1; v2 += b0; v3 += b1;
            }
            float* p0 = C + (size_t)r0 * ldc + c;
            float* p1 = C + (size_t)(r0 + 8) * ldc + c;
            if (atomic) {
                atomicAdd(p0, v0); atomicAdd(p0 + 1, v1);
                atomicAdd(p1, v2); atomicAdd(p1 + 1, v3);
            } else if (accum) {
                p0[0] += v0; p0[1] += v1; p1[0] += v2; p1[1] += v3;
            } else {
                p0[0] = v0; p0[1] = v1; p1[0] = v2; p1[1] = v3;
            }
        }
    }
}

// ---------------- flash attention v5: cp.async double-buffered fp16 --------
static const int SMEM_FLASH_FLOATS = 11552;

__global__ __launch_bounds__(256, 2) void k_flash() {
    extern __shared__ __align__(16) float fsm[];
    __half* sQh = (__half*)fsm;
    __half* sB  = sQh + 2304;
    __half* sPh = sQh + 20736;
    float*  sR  = fsm + 11520;
    int tid = threadIdx.x, lane = tid & 31, warp = tid >> 5;
    int gid = lane >> 2, ctid = lane & 3;
    int hh = blockIdx.y;
    int q0 = blockIdx.x * 32;
    int mg = warp >> 2, nh = warp & 3;
    const float iscale = 0.08838834764831845f;

    unsigned qsb = (unsigned)__cvta_generic_to_shared(sQh);
    unsigned psb = (unsigned)__cvta_generic_to_shared(sPh);
    unsigned b0  = (unsigned)__cvta_generic_to_shared(sB);
    unsigned kb[2] = { b0, b0 + 18432 };
    unsigned vb[2] = { b0 + 9216, b0 + 27648 };
    int q = lane >> 3, r8 = lane & 7;

    {
        int r = tid >> 3, w8 = (tid & 7) * 8;
        const uint4* src = (const uint4*)(g_qkvh + (size_t)(q0 + r) * D3 + hh * 128 + w8 * 2);
        uint4 va = src[0], vbq = src[1];
        *(uint4*)((unsigned*)sQh + r * 36 + w8)     = va;
        *(uint4*)((unsigned*)sQh + r * 36 + w8 + 4) = vbq;
    }
    if (tid < 32) sR[tid] = 0.f;

    int sr = tid >> 2, sg = (tid & 3) * 4;
    const __half* gkv0 = g_qkvh + (size_t)sr * D3 + 256 + hh * 128 + sg * 8;
    unsigned ksoff = sr * 144 + sg * 16;

    {
        const __half* gk = gkv0;
#pragma unroll
        for (int i = 0; i < 4; i++) cpasync16(kb[0] + ksoff + i * 16, gk + i * 8);
#pragma unroll
        for (int i = 0; i < 4; i++) cpasync16(vb[0] + ksoff + i * 16, gk + 256 + i * 8);
        cpcommit();
    }
    __syncthreads();

    unsigned aQ[8][4];
    {
        unsigned base = qsb + ((mg * 16 + (q & 1) * 8 + r8) * 72 + (q >> 1) * 8) * 2;
#pragma unroll
        for (int ks = 0; ks < 8; ks++)
            ldmx4(aQ[ks][0], aQ[ks][1], aQ[ks][2], aQ[ks][3], base + ks * 32);
    }
    unsigned kfoff  = ((nh * 16 + (q & 1) * 8 + r8) * 72 + (q >> 1) * 8) * 2;
    unsigned pfb    = psb + ((mg * 16 + (q & 1) * 8 + r8) * 72 + (q >> 1) * 8) * 2;
    unsigned vfoff0 = (((q & 1) * 8 + r8) * 72 + nh * 32 + (q >> 1) * 8) * 2;

    float oacc[4][4];
#pragma unroll
    for (int nt = 0; nt < 4; nt++)
#pragma unroll
        for (int c = 0; c < 4; c++) oacc[nt][c] = 0.f;
    float prow0 = 0.f, prow1 = 0.f;

    for (int kt = 0; kt < 64; kt++) {
        int b = kt & 1;
        cpwait0();
        __syncthreads();
        if (kt < 63) {
            const __half* gk = gkv0 + (size_t)(kt + 1) * 64 * D3;
            int nb = (kt + 1) & 1;
#pragma unroll
            for (int i = 0; i < 4; i++) cpasync16(kb[nb] + ksoff + i * 16, gk + i * 8);
#pragma unroll
            for (int i = 0; i < 4; i++) cpasync16(vb[nb] + ksoff + i * 16, gk + 256 + i * 8);
            cpcommit();
        }
        float sacc[2][4];
#pragma unroll
        for (int nt = 0; nt < 2; nt++)
#pragma unroll
            for (int c = 0; c < 4; c++) sacc[nt][c] = 0.f;
        unsigned kfb = kb[b] + kfoff;
#pragma unroll
        for (int ks = 0; ks < 8; ks++) {
            unsigned b0n0, b0n1, b1n0, b1n1;
            ldmx4(b0n0, b0n1, b1n0, b1n1, kfb + ks * 32);
            mma_f16(sacc[0][0], sacc[0][1], sacc[0][2], sacc[0][3],
                    aQ[ks][0], aQ[ks][1], aQ[ks][2], aQ[ks][3], b0n0, b1n0);
            mma_f16(sacc[1][0], sacc[1][1], sacc[1][2], sacc[1][3],
                    aQ[ks][0], aQ[ks][1], aQ[ks][2], aQ[ks][3], b0n1, b1n1);
        }
#pragma unroll
        for (int nt = 0; nt < 2; nt++) {
            float p0 = fexp(sacc[nt][0] * iscale);
            float p1 = fexp(sacc[nt][1] * iscale);
            float p2 = fexp(sacc[nt][2] * iscale);
            float p3 = fexp(sacc[nt][3] * iscale);
            __half2 h01 = __floats2half2_rn(p0, p1);
            __half2 h23 = __floats2half2_rn(p2, p3);
            float2 f01 = __half22float2(h01);
            float2 f23 = __half22float2(h23);
            prow0 += f01.x + f01.y;
            prow1 += f23.x + f23.y;
            int w = nh * 8 + nt * 4 + ctid;
            ((unsigned*)sPh)[(mg * 16 + gid) * 36 + w]     = *(unsigned*)&h01;
            ((unsigned*)sPh)[(mg * 16 + gid + 8) * 36 + w] = *(unsigned*)&h23;
        }
        __syncthreads();
        unsigned vfb0 = vb[b] + vfoff0;
        unsigned vfb1 = vfb0 + 32;
#pragma unroll
        for (int kp = 0; kp < 4; kp++) {
            unsigned aP0, aP1, aP2, aP3;
            ldmx4(aP0, aP1, aP2, aP3, pfb + kp * 32);
            unsigned v00, v01, v02, v03, v10, v11, v12, v13;
            ldmx4t(v00, v01, v02, v03, vfb0 + kp * 2304);
            ldmx4t(v10, v11, v12, v13, vfb1 + kp * 2304);
            mma_f16(oacc[0][0], oacc[0][1], oacc[0][2], oacc[0][3],
                    aP0, aP1, aP2, aP3, v00, v01);
            mma_f16(oacc[1][0], oacc[1][1], oacc[1][2], oacc[1][3],
                    aP0, aP1, aP2, aP3, v02, v03);
            mma_f16(oacc[2][0], oacc[2][1], oacc[2][2], oacc[2][3],
                    aP0, aP1, aP2, aP3, v10, v11);
            mma_f16(oacc[3][0], oacc[3][1], oacc[3][2], oacc[3][3],
                    aP0, aP1, aP2, aP3, v12, v13);
        }
    }
    prow0 += __shfl_xor_sync(~0u, prow0, 1);
    prow0 += __shfl_xor_sync(~0u, prow0, 2);
    prow1 += __shfl_xor_sync(~0u, prow1, 1);
    prow1 += __shfl_xor_sync(~0u, prow1, 2);
    if (ctid == 0) {
        atomicAdd(&sR[mg * 16 + gid], prow0);
        atomicAdd(&sR[mg * 16 + gid + 8], prow1);
    }
    __syncthreads();
    float inv0 = 1.f / sR[mg * 16 + gid];
    float inv1 = 1.f / sR[mg * 16 + gid + 8];
    int r0 = q0 + mg * 16 + gid;
#pragma unroll
    for (int nt = 0; nt < 4; nt++) {
        int c = hh * 128 + nh * 32 + nt * 8 + 2 * ctid;
        float* o0 = g_attnO + (size_t)r0 * DD + c;
        float* o1 = g_attnO + (size_t)(r0 + 8) * DD + c;
        o0[0] = oacc[nt][0] * inv0;
        o0[1] = oacc[nt][1] * inv0;
        o1[0] = oacc[nt][2] * inv1;
        o1[1] = oacc[nt][3] * inv1;
    }
}

// ---------------- fused edge MLP v2: ldmatrix everywhere ----------------
// smem floats: h1h/h2h @0 (h1h [64][72]h = 2304f in loop; h2h [256][72]h = 9216f
// in phase3), bb1 @9216, b2 @9728, dm @9984, src/dst @11008, part @11136
static const int SMEM_EDGE_FLOATS = 12160;

__global__ __launch_bounds__(256, 2) void k_edge(
    const void* __restrict__ adj,
    const float* __restrict__ dmv,
    const float* __restrict__ b2,
    const float* __restrict__ b3,
    float* __restrict__ dm_out) {
    extern __shared__ __align__(16) float sm[];
    __half* sh_h1h = (__half*)sm;        // [64][72]
    __half* sh_h2h = (__half*)sm;        // [256][72]
    float*  sh_bb1 = sm + 9216;
    float*  sh_b2  = sm + 9728;
    float*  sh_dm  = sm + 9984;
    int*    sh_src = (int*)(sm + 11008);
    int*    sh_dst = sh_src + 64;
    float*  sh_part = sm + 11136;        // [4][32][8]

    int tid = threadIdx.x;
    int lane = tid & 31, warp = tid >> 5;
    int gid = lane >> 2, ctid = lane & 3;
    int q = lane >> 3, r8 = lane & 7;
    int e0 = blockIdx.x * 64;
    unsigned h1b = (unsigned)__cvta_generic_to_shared(sh_h1h);
    unsigned h2b = (unsigned)__cvta_generic_to_shared(sh_h2h);

    for (int i = tid; i < D2; i += 256) sh_bb1[i] = g_bb1[i];
    for (int i = tid; i < DD; i += 256) sh_b2[i] = b2[i];
    for (int i = tid; i < 64 * DIN; i += 256) sh_dm[i] = dmv[(size_t)e0 * DIN + i];
    if (tid < 64) {
        sh_src[tid] = edge_idx(adj, e0 + tid);
        sh_dst[tid] = edge_idx(adj, NE + e0 + tid);
    }
    __syncthreads();

    int p_k = tid & 63;
    int p_mg = tid >> 6;
    int MT0 = warp * 2, MT1 = MT0 + 1;
    const uint4* w2p4 = (const uint4*)g_w2p;
    // phase-2 B-frag bases (non-trans, h1h rows = edges)
    unsigned bf[4];
#pragma unroll
    for (int p = 0; p < 4; p++)
        bf[p] = h1b + ((p * 16 + (q & 1) * 8 + r8) * 72 + (q >> 1) * 8) * 2;

    float acc0[8][4], acc1[8][4];
#pragma unroll
    for (int nt = 0; nt < 8; nt++)
#pragma unroll
        for (int c = 0; c < 4; c++) { acc0[nt][c] = 0.f; acc1[nt][c] = 0.f; }

    for (int ch = 0; ch < 8; ch++) {
        int kc = ch << 6;
        __syncthreads();
        // phase 1: h1[edge][k] (half) = gelu(bb1 + Ya[src] + Yc[dst] + dm@Meb)
        {
            int j = kc + p_k;
            float mebj[16];
#pragma unroll
            for (int kk = 0; kk < 16; kk++) mebj[kk] = g_Meb[kk * D2 + j];
            float bbj = sh_bb1[j];
#pragma unroll 4
            for (int mi = 0; mi < 16; mi++) {
                int m = p_mg + (mi << 2);
                float v = bbj
                        + g_Ya[(size_t)sh_src[m] * D2 + j]
                        + g_Ya[YCOFF + (size_t)sh_dst[m] * D2 + j];
                const float* dmr = sh_dm + m * 16;
#pragma unroll
                for (int kk = 0; kk < 16; kk++) v += dmr[kk] * mebj[kk];
                sh_h1h[m * 72 + p_k] = __float2half_rn(gelu_f(v));
            }
        }
        __syncthreads();
        // phase 2: accT += w2_tile @ h1^T  (A from packed gmem, B via ldmatrix)
#pragma unroll
        for (int ks = 0; ks < 4; ks++) {
            int KS16 = (ch << 2) + ks;
            uint4 A0 = w2p4[(MT0 * 32 + KS16) * 32 + lane];
            uint4 A1 = w2p4[(MT1 * 32 + KS16) * 32 + lane];
#pragma unroll
            for (int p = 0; p < 4; p++) {
                unsigned bn0k0, bn8k0, bn0k8, bn8k8;
                ldmx4(bn0k0, bn8k0, bn0k8, bn8k8, bf[p] + ks * 32);
                mma_f16(acc0[2*p][0], acc0[2*p][1], acc0[2*p][2], acc0[2*p][3],
                        A0.x, A0.y, A0.z, A0.w, bn0k0, bn0k8);
                mma_f16(acc0[2*p+1][0], acc0[2*p+1][1], acc0[2*p+1][2], acc0[2*p+1][3],
                        A0.x, A0.y, A0.z, A0.w, bn8k0, bn8k8);
                mma_f16(acc1[2*p][0], acc1[2*p][1], acc1[2*p][2], acc1[2*p][3],
                        A1.x, A1.y, A1.z, A1.w, bn0k0, bn0k8);
                mma_f16(acc1[2*p+1][0], acc1[2*p+1][1], acc1[2*p+1][2], acc1[2*p+1][3],
                        A1.x, A1.y, A1.z, A1.w, bn8k0, bn8k8);
            }
        }
    }
    __syncthreads();
    // phase 3a: h2h[outcol][edge] = half(gelu(accT + b2)), packed half2 stores
    {
        int r0 = warp * 32 + gid;
        int r1 = warp * 32 + 16 + gid;
        float br0 = sh_b2[r0], br0b = sh_b2[r0 + 8];
        float br1 = sh_b2[r1], br1b = sh_b2[r1 + 8];
        unsigned* h2w = (unsigned*)sh_h2h;
#pragma unroll
        for (int nt = 0; nt < 8; nt++) {
            int wq = nt * 4 + ctid;
            h2w[r0 * 36 + wq]       = h2pack(gelu_f(acc0[nt][0] + br0),  gelu_f(acc0[nt][1] + br0));
            h2w[(r0 + 8) * 36 + wq] = h2pack(gelu_f(acc0[nt][2] + br0b), gelu_f(acc0[nt][3] + br0b));
            h2w[r1 * 36 + wq]       = h2pack(gelu_f(acc1[nt][0] + br1),  gelu_f(acc1[nt][1] + br1));
            h2w[(r1 + 8) * 36 + wq] = h2pack(gelu_f(acc1[nt][2] + br1b), gelu_f(acc1[nt][3] + br1b));
        }
    }
    __syncthreads();
    // phase 3b: dm_out^T = w3 @ h2h  via mma; warps: ng = w&3 (16 edges), kh = w>>2
    {
        int ng = warp & 3, kh = warp >> 2;
        const uint4* w3p4 = (const uint4*)g_w3p;
        float pacc[2][4];
#pragma unroll
        for (int f = 0; f < 2; f++)
#pragma unroll
            for (int c = 0; c < 4; c++) pacc[f][c] = 0.f;
        unsigned vbase = h2b + (((q & 1) * 8 + r8) * 72 + ng * 16 + (q >> 1) * 8) * 2;
#pragma unroll
        for (int ks = 0; ks < 8; ks++) {
            int KS = kh * 8 + ks;
            uint4 A = w3p4[KS * 32 + lane];
            unsigned v00, v01, v02, v03;
            ldmx4t(v00, v01, v02, v03, vbase + KS * 16 * 144);
            mma_f16(pacc[0][0], pacc[0][1], pacc[0][2], pacc[0][3],
                    A.x, A.y, A.z, A.w, v00, v01);
            mma_f16(pacc[1][0], pacc[1][1], pacc[1][2], pacc[1][3],
                    A.x, A.y, A.z, A.w, v02, v03);
        }
        if (kh == 1) {
#pragma unroll
            for (int f = 0; f < 2; f++)
#pragma unroll
                for (int c = 0; c < 4; c++)
                    sh_part[ng * 256 + lane * 8 + f * 4 + c] = pacc[f][c];
        }
        __syncthreads();
        if (kh == 0) {
#pragma unroll
            for (int f = 0; f < 2; f++) {
                int e = ng * 16 + f * 8 + 2 * ctid;
                float v0 = pacc[f][0] + sh_part[ng * 256 + lane * 8 + f * 4 + 0];
                float v1 = pacc[f][1] + sh_part[ng * 256 + lane * 8 + f * 4 + 1];
                float v2 = pacc[f][2] + sh_part[ng * 256 + lane * 8 + f * 4 + 2];
                float v3 = pacc[f][3] + sh_part[ng * 256 + lane * 8 + f * 4 + 3];
                float b3lo = b3[gid], b3hi = b3[gid + 8];
                dm_out[(size_t)(e0 + e) * 16 + gid]         = v0 + b3lo;
                dm_out[(size_t)(e0 + e + 1) * 16 + gid]     = v1 + b3lo;
                dm_out[(size_t)(e0 + e) * 16 + gid + 8]     = v2 + b3hi;
                dm_out[(size_t)(e0 + e + 1) * 16 + gid + 8] = v3 + b3hi;
            }
        }
    }
}

// ---------------- epilogue ----------------
__global__ void k_epilogue(const float* __restrict__ h0,
                           const float* __restrict__ alpha,
                           float* __restrict__ out) {
    int i = blockIdx.x * 256 + threadIdx.x;
    int n = i >> 8, d = i & 255;
    float a = alpha[0];
    const float theta = 0.69314718055994531f;
    float xo = g_cat[(size_t)n * D3 + d];
    float hg = g_cat[(size_t)n * D3 + 256 + d];
    float r = (1.f - a) * (xo + hg) + 2.f * a * h0[i];
    out[i] = g_tmp[i] + (1.f - theta) * r;
}

// ---------------- host ----------------
static float* sym_addr(const void* sym) {
    void* p = nullptr;
    cudaGetSymbolAddress(&p, sym);
    return (float*)p;
}

struct HxRes {
    cudaStream_t s2;
    cudaEvent_t ef, ej, efin;
    HxRes() {
        cudaStreamCreateWithFlags(&s2, cudaStreamNonBlocking);
        cudaEventCreateWithFlags(&ef, cudaEventDisableTiming);
        cudaEventCreateWithFlags(&ej, cudaEventDisableTiming);
        cudaEventCreateWithFlags(&efin, cudaEventDisableTiming);
    }
};

extern "C" void kernel_launch(void* const* d_in, const int* in_sizes, int n_in,
                              void* d_out, int out_size) {
    static HxRes R;

    int I_in = 0, I_adj = 1, I_h0 = 2, I_al, I_dm, I_nm, I_wl, I_wg, I_lw, I_lb,
        I_w1, I_b1, I_w2, I_b2, I_w3, I_b3, I_ipw, I_ipb, I_opw, I_opb;
    if (n_in >= 22) {
        I_al = 4; I_dm = 6; I_nm = 7; I_wl = 8; I_wg = 9; I_lw = 10; I_lb = 11;
        I_w1 = 12; I_b1 = 13; I_w2 = 14; I_b2 = 15; I_w3 = 16; I_b3 = 17;
        I_ipw = 18; I_ipb = 19; I_opw = 20; I_opb = 21;
    } else {
        I_al = 3; I_dm = 4; I_nm = 5; I_wl = 6; I_wg = 7; I_lw = 8; I_lb = 9;
        I_w1 = 10; I_b1 = 11; I_w2 = 12; I_b2 = 13; I_w3 = 14; I_b3 = 15;
        I_ipw = 16; I_ipb = 17; I_opw = 18; I_opb = 19;
    }
    const float* input = (const float*)d_in[I_in];
    const void*  adj   = d_in[I_adj];
    const float* h0    = (const float*)d_in[I_h0];
    const float* alpha = (const float*)d_in[I_al];
    const float* dmap  = (const float*)d_in[I_dm];
    const float* norm  = (const float*)d_in[I_nm];
    const float* Wl    = (const float*)d_in[I_wl];
    const float* Wg    = (const float*)d_in[I_wg];
    const float* lin_w = (const float*)d_in[I_lw];
    const float* lin_b = (const float*)d_in[I_lb];
    const float* w1    = (const float*)d_in[I_w1];
    const float* b1    = (const float*)d_in[I_b1];
    const float* w2    = (const float*)d_in[I_w2];
    const float* b2    = (const float*)d_in[I_b2];
    const float* w3    = (const float*)d_in[I_w3];
    const float* b3    = (const float*)d_in[I_b3];
    const float* ipw   = (const float*)d_in[I_ipw];
    const float* ipb   = (const float*)d_in[I_ipb];
    const float* opw   = (const float*)d_in[I_opw];
    const float* opb   = (const float*)d_in[I_opb];

    float* out    = (float*)d_out;
    float* dm_out = out + (size_t)NN * DD;

    float* cat    = sym_addr(g_cat);
    float* Ya     = sym_addr(g_Ya);
    float* qkv    = sym_addr(g_qkv);
    float* attnO  = sym_addr(g_attnO);
    float* tmp    = sym_addr(g_tmp);

    cudaFuncSetAttribute(k_edge, cudaFuncAttributeMaxDynamicSharedMemorySize,
                         SMEM_EDGE_FLOATS * 4);
    cudaFuncSetAttribute(k_flash, cudaFuncAttributeMaxDynamicSharedMemorySize,
                         SMEM_FLASH_FLOATS * 4);

    const float theta = 0.69314718055994531f;

    cudaEventRecord(R.ef, 0);
    cudaStreamWaitEvent(R.s2, R.ef, 0);

    k_detect<<<1, 32>>>(adj);
    k_init<<<8464, 256>>>(input, h0);
    k_scatter<<<16384, 256>>>(adj, input, dmap, norm);
    gemm_tc<<<dim3(6, 32), 256, 0, R.s2>>>(input, DD, ipw, DD, qkv, D3, DD, 1.f, ipb, 0, 1, 0, 0, 0);
    k_qkvh<<<3072, 256, 0, R.s2>>>();
    k_flash<<<dim3(128, 2), 256, SMEM_FLASH_FLOATS * 4, R.s2>>>();
    gemm_tc<<<dim3(2, 32), 256, 0, R.s2>>>(attnO, DD, opw, DD, cat + 256, D3, DD, 1.f, opb, 0, 1, 0, 0, 0);
    gemm_tc<<<dim3(2, 32), 256, 0, R.s2>>>(cat + 256, D3, Wg,            DD, tmp, DD, DD, theta, nullptr, 0, 0, 0, 0, 0);
    gemm_tc<<<dim3(2, 32), 256, 0, R.s2>>>(cat + 512, D3, Wl + DD * DD,  DD, tmp, DD, DD, theta, nullptr, 1, 0, 0, 0, 0);
    gemm_tc<<<dim3(2, 32), 256, 0, R.s2>>>(cat + 512, D3, Wg + DD * DD,  DD, tmp, DD, DD, theta, nullptr, 1, 0, 0, 0, 0);

    k_meb<<<16, 256>>>(lin_w, lin_b, w1, b1);
    k_w2pack<<<66, 256>>>(w2, w3);
    k_finalize_xout<<<4096, 256>>>(lin_w, lin_b);
    cudaEventRecord(R.efin, 0);

    cudaStreamWaitEvent(R.s2, R.efin, 0);
    gemm_tc<<<dim3(2, 32), 256, 0, R.s2>>>(cat, D3, Wl, DD, tmp, DD, DD, theta, nullptr, 1, 0, 0, 0, 0);
    cudaEventRecord(R.ej, R.s2);

    gemm_tc<<<dim3(4, 32, 2), 256>>>(cat, D3, w1, D3, Ya, D2, DD, 1.f, nullptr, 0, 1, 0,
                                     512, (long)NN * D2);

    k_edge<<<2048, 256, SMEM_EDGE_FLOATS * 4>>>(adj, dmap, b2, b3, dm_out);

    cudaStreamWaitEvent(0, R.ej, 0);
    k_epilogue<<<4096, 256>>>(h0, alpha, out);
}

// round 16
// speedup vs baseline: 1.3947x; 1.3947x over previous
#include <cuda_runtime.h>
#include <cuda_fp16.h>
#include <math.h>
#include <stdint.h>

static const int NN  = 4096;
static const int NE  = 131072;
static const int DD  = 256;
static const int DIN = 16;
static const int D2  = 512;
static const int D3  = 768;
static const int YCOFF = NN * D2;   // offset of Yc inside g_Ya

// ---------------- device scratch ----------------
__device__ float g_xacc[NN * DD];
__device__ float g_S[NN * 17];
__device__ float g_cat[NN * D3];          // [xout | hglob | h0]
__device__ float g_Ya[2 * NN * D2];       // [Ya | Yc]
__device__ float g_Meb[DIN * D2];
__device__ float g_bb1[D2];
__device__ float g_w2p[16 * 64 * 32 * 4]; // fragment-packed w2 (fp16 m16n8k16 frags)
__device__ float g_qkv[NN * D3];
__device__ __half g_qkvh[NN * D3];        // fp16 copy for flash staging
__device__ float g_attnO[NN * DD];
__device__ float g_tmp[NN * DD];
__device__ int   g_is64;

__device__ __forceinline__ float gelu_f(float x) {
    return 0.5f * x * (1.f + erff(x * 0.70710678118654752f));
}

__device__ __forceinline__ unsigned tf32r(float x) {
    unsigned u;
    asm("cvt.rna.tf32.f32 %0, %1;" : "=r"(u) : "f"(x));
    return u;
}
__device__ __forceinline__ float tf32f(float x) {
    return __uint_as_float(tf32r(x));
}

__device__ __forceinline__ unsigned h2pack(float x, float y) {
    __half2 h = __floats2half2_rn(x, y);
    return *(unsigned*)&h;
}

// m16n8k8 tf32 mma
__device__ __forceinline__ void mma_tf32(
    float& c0, float& c1, float& c2, float& c3,
    unsigned a0, unsigned a1, unsigned a2, unsigned a3,
    unsigned b0, unsigned b1) {
    asm("mma.sync.aligned.m16n8k8.row.col.f32.tf32.tf32.f32 "
        "{%0,%1,%2,%3}, {%4,%5,%6,%7}, {%8,%9}, {%0,%1,%2,%3};"
        : "+f"(c0), "+f"(c1), "+f"(c2), "+f"(c3)
        : "r"(a0), "r"(a1), "r"(a2), "r"(a3), "r"(b0), "r"(b1));
}

// m16n8k16 fp16 mma (fp32 accum)
__device__ __forceinline__ void mma_f16(
    float& c0, float& c1, float& c2, float& c3,
    unsigned a0, unsigned a1, unsigned a2, unsigned a3,
    unsigned b0, unsigned b1) {
    asm("mma.sync.aligned.m16n8k16.row.col.f32.f16.f16.f32 "
        "{%0,%1,%2,%3}, {%4,%5,%6,%7}, {%8,%9}, {%0,%1,%2,%3};"
        : "+f"(c0), "+f"(c1), "+f"(c2), "+f"(c3)
        : "r"(a0), "r"(a1), "r"(a2), "r"(a3), "r"(b0), "r"(b1));
}

__device__ __forceinline__ void ldmx4(unsigned& r0, unsigned& r1, unsigned& r2, unsigned& r3,
                                      unsigned addr) {
    asm volatile("ldmatrix.sync.aligned.m8n8.x4.shared.b16 {%0,%1,%2,%3}, [%4];"
                 : "=r"(r0), "=r"(r1), "=r"(r2), "=r"(r3) : "r"(addr));
}
__device__ __forceinline__ void ldmx4t(unsigned& r0, unsigned& r1, unsigned& r2, unsigned& r3,
                                       unsigned addr) {
    asm volatile("ldmatrix.sync.aligned.m8n8.x4.trans.shared.b16 {%0,%1,%2,%3}, [%4];"
                 : "=r"(r0), "=r"(r1), "=r"(r2), "=r"(r3) : "r"(addr));
}

__device__ __forceinline__ void cpasync16(unsigned saddr, const void* g) {
    asm volatile("cp.async.cg.shared.global [%0], [%1], 16;" :: "r"(saddr), "l"(g));
}
__device__ __forceinline__ void cpcommit() {
    asm volatile("cp.async.commit_group;");
}
__device__ __forceinline__ void cpwait0() {
    asm volatile("cp.async.wait_group 0;");
}

// fast exp (FFMA-only 2^x poly)
__device__ __forceinline__ float fexp(float x) {
    float t = fmaxf(x * 1.442695041f, -126.f);
    float fi = floorf(t);
    float f = t - fi;
    float p = 1.33336e-3f;
    p = fmaf(p, f, 9.61813e-3f);
    p = fmaf(p, f, 5.55041e-2f);
    p = fmaf(p, f, 2.40226e-1f);
    p = fmaf(p, f, 6.93147e-1f);
    p = fmaf(p, f, 1.0f);
    return p * __int_as_float(((int)fi + 127) << 23);
}

// vector reduction atomic (sm_90+)
__device__ __forceinline__ void red4(float* p, float a, float b, float c, float d) {
    asm volatile("red.global.add.v4.f32 [%0], {%1,%2,%3,%4};"
                 :: "l"(p), "f"(a), "f"(b), "f"(c), "f"(d) : "memory");
}

// ---------------- adj dtype detection ----------------
__global__ void k_detect(const void* __restrict__ adj) {
    if (threadIdx.x == 0) {
        const long long* a = (const long long*)adj;
        int ok = 1;
        for (int e = 0; e < 64; e++) {
            long long v = a[e];
            if (v < 0 || v >= NN) ok = 0;
        }
        g_is64 = ok;
    }
}
__device__ __forceinline__ int edge_idx(const void* adj, int i) {
    if (g_is64) return (int)((const long long*)adj)[i];
    return ((const int*)adj)[i];
}

// ---------------- init: xacc=input, S=0, cat[:,512:768]=h0 ----------------
__global__ void k_init(const float* __restrict__ input,
                       const float* __restrict__ h0) {
    int i = blockIdx.x * 256 + threadIdx.x;
    const int NM = NN * DD;
    const int NS = NN * 17;
    if (i < NM) g_xacc[i] = input[i];
    else if (i < NM + NS) g_S[i - NM] = 0.f;
    else if (i < 2 * NM + NS) {
        int j = i - NM - NS;
        g_cat[(size_t)(j >> 8) * D3 + 512 + (j & 255)] = h0[j];
    }
}

// ---------------- qkv -> fp16 ----------------
__global__ void k_qkvh() {
    int i = blockIdx.x * 256 + threadIdx.x;
    float4 v = ((const float4*)g_qkv)[i];
    uint2 o;
    o.x = h2pack(v.x, v.y);
    o.y = h2pack(v.z, v.w);
    ((uint2*)g_qkvh)[i] = o;
}

// ---------------- scatter ----------------
__global__ void k_scatter(const void* __restrict__ adj,
                          const float* __restrict__ x,
                          const float* __restrict__ dmv,
                          const float* __restrict__ norm) {
    int e = blockIdx.x * 8 + (threadIdx.x >> 5);
    int lane = threadIdx.x & 31;
    int src = edge_idx(adj, e);
    int dst = edge_idx(adj, NE + e);
    float nrm = norm[e];
    const float4* xr = (const float4*)(x + (size_t)src * DD);
    float* out = g_xacc + (size_t)dst * DD;
#pragma unroll
    for (int t = 0; t < 2; t++) {
        float4 v = xr[lane + t * 32];
        int c = (lane + t * 32) * 4;
        red4(out + c, nrm * v.x, nrm * v.y, nrm * v.z, nrm * v.w);
    }
    if (lane < DIN)       atomicAdd(&g_S[dst * 17 + lane], nrm * dmv[(size_t)e * DIN + lane]);
    else if (lane == DIN) atomicAdd(&g_S[dst * 17 + 16], nrm);
}

// ---------------- x_out -> g_cat[:,0:256] ----------------
__global__ void k_finalize_xout(const float* __restrict__ lin_w,
                                const float* __restrict__ lin_b) {
    int i = blockIdx.x * 256 + threadIdx.x;
    int n = i >> 8, d = i & 255;
    const float* Sr = g_S + n * 17;
    float v = g_xacc[i];
#pragma unroll
    for (int k = 0; k < 16; k++) v += Sr[k] * lin_w[d * 16 + k];
    v += Sr[16] * lin_b[d];
    g_cat[(size_t)n * D3 + d] = v;
}

// ---------------- precompute Meb, bb1 ----------------
__global__ void k_meb(const float* __restrict__ lin_w, const float* __restrict__ lin_b,
                      const float* __restrict__ w1, const float* __restrict__ b1) {
    int k = blockIdx.x;
    for (int j = threadIdx.x; j < D2; j += 256) {
        const float* wr = w1 + (size_t)j * D3 + DD;
        float acc = 0.f;
        for (int d = 0; d < DD; d++) acc += lin_w[d * 16 + k] * wr[d];
        g_Meb[k * D2 + j] = acc;
        if (k == 0) {
            float lb = 0.f;
            for (int d = 0; d < DD; d++) lb += lin_b[d] * wr[d];
            g_bb1[j] = b1[j] + lb;
        }
    }
}

// ---------------- pack w2 into fp16 m16n8k16 fragments ----------------
__global__ void k_w2pack(const float* __restrict__ w2) {
    int t = blockIdx.x * 256 + threadIdx.x;  // 16384
    int lane = t & 31;
    int KS = (t >> 5) & 31;
    int MT = t >> 10;
    int gid = lane >> 2, ctid = lane & 3;
    int r0 = MT * 16 + gid, c0 = KS * 16 + 2 * ctid;
    uint4 v;
    v.x = h2pack(w2[(size_t)r0 * D2 + c0],       w2[(size_t)r0 * D2 + c0 + 1]);
    v.y = h2pack(w2[(size_t)(r0 + 8) * D2 + c0], w2[(size_t)(r0 + 8) * D2 + c0 + 1]);
    v.z = h2pack(w2[(size_t)r0 * D2 + c0 + 8],   w2[(size_t)r0 * D2 + c0 + 9]);
    v.w = h2pack(w2[(size_t)(r0 + 8) * D2 + c0 + 8], w2[(size_t)(r0 + 8) * D2 + c0 + 9]);
    ((uint4*)g_w2p)[t] = v;
}

// ---------------- tf32 tensor-core GEMM: 128x128 tile ----------------
__global__ __launch_bounds__(256) void gemm_tc(
    const float* __restrict__ A, int lda,
    const float* __restrict__ B, int ldb,
    float* __restrict__ C, int ldc,
    int K, float alpha, const float* __restrict__ bias,
    int accum, int transB, int atomic, int zbo, long zco) {
    __shared__ float As[128 * 36];
    __shared__ float Bs[128 * 36];
    int tid = threadIdx.x, lane = tid & 31, warp = tid >> 5;
    int gid = lane >> 2, ctid = lane & 3;
    int m0 = blockIdx.y << 7, j0 = blockIdx.x << 7;
    int kbase;
    if (zco != 0) {
        B += (size_t)blockIdx.z * zbo;
        C += (size_t)blockIdx.z * zco;
        kbase = 0;
    } else {
        kbase = blockIdx.z * K;
    }
    int wm = (warp >> 2) << 6;
    int wn = (warp & 3) << 5;
    int arow = tid >> 1, acol = (tid & 1) << 4;
    float acc[4][4][4];
#pragma unroll
    for (int a = 0; a < 4; a++)
#pragma unroll
        for (int b = 0; b < 4; b++)
#pragma unroll
            for (int c = 0; c < 4; c++) acc[a][b][c] = 0.f;

    for (int k0 = kbase; k0 < kbase + K; k0 += 32) {
        __syncthreads();
        {
            const float* ap = A + (size_t)(m0 + arow) * lda + k0 + acol;
            float* asp = As + arow * 36 + acol;
#pragma unroll
            for (int i = 0; i < 4; i++) {
                float4 v = *(const float4*)(ap + 4 * i);
                asp[4 * i + 0] = tf32f(v.x);
                asp[4 * i + 1] = tf32f(v.y);
                asp[4 * i + 2] = tf32f(v.z);
                asp[4 * i + 3] = tf32f(v.w);
            }
        }
        if (transB) {
            const float* bp = B + (size_t)(j0 + arow) * ldb + k0 + acol;
            float* bsp = Bs + arow * 36 + acol;
#pragma unroll
            for (int i = 0; i < 4; i++) {
                float4 v = *(const float4*)(bp + 4 * i);
                bsp[4 * i + 0] = tf32f(v.x);
                bsp[4 * i + 1] = tf32f(v.y);
                bsp[4 * i + 2] = tf32f(v.z);
                bsp[4 * i + 3] = tf32f(v.w);
            }
        } else {
            int kr = tid >> 3, nc = (tid & 7) << 4;
            const float* bp = B + (size_t)(k0 + kr) * ldb + j0 + nc;
#pragma unroll
            for (int i = 0; i < 4; i++) {
                float4 v = *(const float4*)(bp + 4 * i);
                Bs[(nc + 4 * i + 0) * 36 + kr] = tf32f(v.x);
                Bs[(nc + 4 * i + 1) * 36 + kr] = tf32f(v.y);
                Bs[(nc + 4 * i + 2) * 36 + kr] = tf32f(v.z);
                Bs[(nc + 4 * i + 3) * 36 + kr] = tf32f(v.w);
            }
        }
        __syncthreads();
#pragma unroll
        for (int ks = 0; ks < 4; ks++) {
            int kk = ks << 3;
            unsigned a[4][4], b[4][2];
#pragma unroll
            for (int mt = 0; mt < 4; mt++) {
                const float* p = As + (wm + mt * 16 + gid) * 36 + kk + ctid;
                a[mt][0] = __float_as_uint(p[0]);
                a[mt][1] = __float_as_uint(p[8 * 36]);
                a[mt][2] = __float_as_uint(p[4]);
                a[mt][3] = __float_as_uint(p[8 * 36 + 4]);
            }
#pragma unroll
            for (int nt = 0; nt < 4; nt++) {
                const float* q = Bs + (wn + nt * 8 + gid) * 36 + kk + ctid;
                b[nt][0] = __float_as_uint(q[0]);
                b[nt][1] = __float_as_uint(q[4]);
            }
#pragma unroll
            for (int mt = 0; mt < 4; mt++)
#pragma unroll
                for (int nt = 0; nt < 4; nt++)
                    mma_tf32(acc[mt][nt][0], acc[mt][nt][1], acc[mt][nt][2], acc[mt][nt][3],
                             a[mt][0], a[mt][1], a[mt][2], a[mt][3],
                             b[nt][0], b[nt][1]);
        }
    }
#pragma unroll
    for (int mt = 0; mt < 4; mt++) {
#pragma unroll
        for (int nt = 0; nt < 4; nt++) {
            int r0 = m0 + wm + mt * 16 + gid;
            int c = j0 + wn + nt * 8 + 2 * ctid;
            float v0 = alpha * acc[mt][nt][0], v1 = alpha * acc[mt][nt][1];
            float v2 = alpha * acc[mt][nt][2], v3 = alpha * acc[mt][nt][3];
            if (bias) {
                float b0 = bias[c], b1 = bias[c + 1];
                v0 += b0; v1 += b1; v2 += b0; v3 += b1;
            }
            float* p0 = C + (size_t)r0 * ldc + c;
            float* p1 = C + (size_t)(r0 + 8) * ldc + c;
            if (atomic) {
                atomicAdd(p0, v0); atomicAdd(p0 + 1, v1);
                atomicAdd(p1, v2); atomicAdd(p1 + 1, v3);
            } else if (accum) {
                p0[0] += v0; p0[1] += v1; p1[0] += v2; p1[1] += v3;
            } else {
                p0[0] = v0; p0[1] = v1; p1[0] = v2; p1[1] = v3;
            }
        }
    }
}

// ---------------- flash attention v5: cp.async double-buffered fp16 --------
static const int SMEM_FLASH_FLOATS = 11552;

__global__ __launch_bounds__(256, 2) void k_flash() {
    extern __shared__ __align__(16) float fsm[];
    __half* sQh = (__half*)fsm;
    __half* sB  = sQh + 2304;
    __half* sPh = sQh + 20736;
    float*  sR  = fsm + 11520;
    int tid = threadIdx.x, lane = tid & 31, warp = tid >> 5;
    int gid = lane >> 2, ctid = lane & 3;
    int hh = blockIdx.y;
    int q0 = blockIdx.x * 32;
    int mg = warp >> 2, nh = warp & 3;
    const float iscale = 0.08838834764831845f;

    unsigned qsb = (unsigned)__cvta_generic_to_shared(sQh);
    unsigned psb = (unsigned)__cvta_generic_to_shared(sPh);
    unsigned b0  = (unsigned)__cvta_generic_to_shared(sB);
    unsigned kb[2] = { b0, b0 + 18432 };
    unsigned vb[2] = { b0 + 9216, b0 + 27648 };
    int q = lane >> 3, r8 = lane & 7;

    {
        int r = tid >> 3, w8 = (tid & 7) * 8;
        const uint4* src = (const uint4*)(g_qkvh + (size_t)(q0 + r) * D3 + hh * 128 + w8 * 2);
        uint4 va = src[0], vbq = src[1];
        *(uint4*)((unsigned*)sQh + r * 36 + w8)     = va;
        *(uint4*)((unsigned*)sQh + r * 36 + w8 + 4) = vbq;
    }
    if (tid < 32) sR[tid] = 0.f;

    int sr = tid >> 2, sg = (tid & 3) * 4;
    const __half* gkv0 = g_qkvh + (size_t)sr * D3 + 256 + hh * 128 + sg * 8;
    unsigned ksoff = sr * 144 + sg * 16;

    {
        const __half* gk = gkv0;
#pragma unroll
        for (int i = 0; i < 4; i++) cpasync16(kb[0] + ksoff + i * 16, gk + i * 8);
#pragma unroll
        for (int i = 0; i < 4; i++) cpasync16(vb[0] + ksoff + i * 16, gk + 256 + i * 8);
        cpcommit();
    }
    __syncthreads();

    unsigned aQ[8][4];
    {
        unsigned base = qsb + ((mg * 16 + (q & 1) * 8 + r8) * 72 + (q >> 1) * 8) * 2;
#pragma unroll
        for (int ks = 0; ks < 8; ks++)
            ldmx4(aQ[ks][0], aQ[ks][1], aQ[ks][2], aQ[ks][3], base + ks * 32);
    }
    unsigned kfoff  = ((nh * 16 + (q & 1) * 8 + r8) * 72 + (q >> 1) * 8) * 2;
    unsigned pfb    = psb + ((mg * 16 + (q & 1) * 8 + r8) * 72 + (q >> 1) * 8) * 2;
    unsigned vfoff0 = (((q & 1) * 8 + r8) * 72 + nh * 32 + (q >> 1) * 8) * 2;

    float oacc[4][4];
#pragma unroll
    for (int nt = 0; nt < 4; nt++)
#pragma unroll
        for (int c = 0; c < 4; c++) oacc[nt][c] = 0.f;
    float prow0 = 0.f, prow1 = 0.f;

    for (int kt = 0; kt < 64; kt++) {
        int b = kt & 1;
        cpwait0();
        __syncthreads();
        if (kt < 63) {
            const __half* gk = gkv0 + (size_t)(kt + 1) * 64 * D3;
            int nb = (kt + 1) & 1;
#pragma unroll
            for (int i = 0; i < 4; i++) cpasync16(kb[nb] + ksoff + i * 16, gk + i * 8);
#pragma unroll
            for (int i = 0; i < 4; i++) cpasync16(vb[nb] + ksoff + i * 16, gk + 256 + i * 8);
            cpcommit();
        }
        float sacc[2][4];
#pragma unroll
        for (int nt = 0; nt < 2; nt++)
#pragma unroll
            for (int c = 0; c < 4; c++) sacc[nt][c] = 0.f;
        unsigned kfb = kb[b] + kfoff;
#pragma unroll
        for (int ks = 0; ks < 8; ks++) {
            unsigned b0n0, b0n1, b1n0, b1n1;
            ldmx4(b0n0, b0n1, b1n0, b1n1, kfb + ks * 32);
            mma_f16(sacc[0][0], sacc[0][1], sacc[0][2], sacc[0][3],
                    aQ[ks][0], aQ[ks][1], aQ[ks][2], aQ[ks][3], b0n0, b1n0);
            mma_f16(sacc[1][0], sacc[1][1], sacc[1][2], sacc[1][3],
                    aQ[ks][0], aQ[ks][1], aQ[ks][2], aQ[ks][3], b0n1, b1n1);
        }
#pragma unroll
        for (int nt = 0; nt < 2; nt++) {
            float p0 = fexp(sacc[nt][0] * iscale);
            float p1 = fexp(sacc[nt][1] * iscale);
            float p2 = fexp(sacc[nt][2] * iscale);
            float p3 = fexp(sacc[nt][3] * iscale);
            __half2 h01 = __floats2half2_rn(p0, p1);
            __half2 h23 = __floats2half2_rn(p2, p3);
            float2 f01 = __half22float2(h01);
            float2 f23 = __half22float2(h23);
            prow0 += f01.x + f01.y;
            prow1 += f23.x + f23.y;
            int w = nh * 8 + nt * 4 + ctid;
            ((unsigned*)sPh)[(mg * 16 + gid) * 36 + w]     = *(unsigned*)&h01;
            ((unsigned*)sPh)[(mg * 16 + gid + 8) * 36 + w] = *(unsigned*)&h23;
        }
        __syncthreads();
        unsigned vfb0 = vb[b] + vfoff0;
        unsigned vfb1 = vfb0 + 32;
#pragma unroll
        for (int kp = 0; kp < 4; kp++) {
            unsigned aP0, aP1, aP2, aP3;
            ldmx4(aP0, aP1, aP2, aP3, pfb + kp * 32);
            unsigned v00, v01, v02, v03, v10, v11, v12, v13;
            ldmx4t(v00, v01, v02, v03, vfb0 + kp * 2304);
            ldmx4t(v10, v11, v12, v13, vfb1 + kp * 2304);
            mma_f16(oacc[0][0], oacc[0][1], oacc[0][2], oacc[0][3],
                    aP0, aP1, aP2, aP3, v00, v01);
            mma_f16(oacc[1][0], oacc[1][1], oacc[1][2], oacc[1][3],
                    aP0, aP1, aP2, aP3, v02, v03);
            mma_f16(oacc[2][0], oacc[2][1], oacc[2][2], oacc[2][3],
                    aP0, aP1, aP2, aP3, v10, v11);
            mma_f16(oacc[3][0], oacc[3][1], oacc[3][2], oacc[3][3],
                    aP0, aP1, aP2, aP3, v12, v13);
        }
    }
    prow0 += __shfl_xor_sync(~0u, prow0, 1);
    prow0 += __shfl_xor_sync(~0u, prow0, 2);
    prow1 += __shfl_xor_sync(~0u, prow1, 1);
    prow1 += __shfl_xor_sync(~0u, prow1, 2);
    if (ctid == 0) {
        atomicAdd(&sR[mg * 16 + gid], prow0);
        atomicAdd(&sR[mg * 16 + gid + 8], prow1);
    }
    __syncthreads();
    float inv0 = 1.f / sR[mg * 16 + gid];
    float inv1 = 1.f / sR[mg * 16 + gid + 8];
    int r0 = q0 + mg * 16 + gid;
#pragma unroll
    for (int nt = 0; nt < 4; nt++) {
        int c = hh * 128 + nh * 32 + nt * 8 + 2 * ctid;
        float* o0 = g_attnO + (size_t)r0 * DD + c;
        float* o1 = g_attnO + (size_t)(r0 + 8) * DD + c;
        o0[0] = oacc[nt][0] * inv0;
        o0[1] = oacc[nt][1] * inv0;
        o1[0] = oacc[nt][2] * inv1;
        o1[1] = oacc[nt][3] * inv1;
    }
}

// ---------------- fused edge MLP (R14 version + double-buffered h1) --------
static const int SMEM_EDGE_FLOATS = 23424;

__global__ __launch_bounds__(256, 2) void k_edge(
    const void* __restrict__ adj,
    const float* __restrict__ dmv,
    const float* __restrict__ b2,
    const float* __restrict__ w3,
    const float* __restrict__ b3,
    float* __restrict__ dm_out) {
    extern __shared__ __align__(16) float sm[];
    float*  sh_h2  = sm;                 // [256][68] floats
    float*  sh_bb1 = sm + 17408;
    float*  sh_b2  = sm + 17920;
    float*  sh_w3  = sm + 18176;
    float*  sh_dm  = sm + 22272;
    int*    sh_src = (int*)(sm + 23296);
    int*    sh_dst = sh_src + 64;

    int tid = threadIdx.x;
    int lane = tid & 31, warp = tid >> 5;
    int gid = lane >> 2, ctid = lane & 3;
    int e0 = blockIdx.x * 64;

    for (int i = tid; i < D2; i += 256) sh_bb1[i] = g_bb1[i];
    for (int i = tid; i < DD; i += 256) sh_b2[i] = b2[i];
    for (int i = tid; i < DIN * DD; i += 256) sh_w3[i] = w3[i];
    for (int i = tid; i < 64 * DIN; i += 256) sh_dm[i] = dmv[(size_t)e0 * DIN + i];
    if (tid < 64) {
        sh_src[tid] = edge_idx(adj, e0 + tid);
        sh_dst[tid] = edge_idx(adj, NE + e0 + tid);
    }
    __syncthreads();

    int p_k = tid & 63;
    int p_mg = tid >> 6;
    int MT0 = warp * 2, MT1 = MT0 + 1;
    const uint4* w2p4 = (const uint4*)g_w2p;

    float acc0[8][4], acc1[8][4];
#pragma unroll
    for (int nt = 0; nt < 8; nt++)
#pragma unroll
        for (int c = 0; c < 4; c++) { acc0[nt][c] = 0.f; acc1[nt][c] = 0.f; }

    for (int ch = 0; ch < 8; ch++) {
        int kc = ch << 6;
        // double-buffered h1: buffer (ch & 1) at float offset (ch&1)*2304
        __half* h1c = (__half*)(sm + ((ch & 1) ? 2304 : 0));
        // phase 1: h1[edge][k] (half) = gelu(bb1 + Ya[src] + Yc[dst] + dm@Meb)
        {
            int j = kc + p_k;
            float mebj[16];
#pragma unroll
            for (int kk = 0; kk < 16; kk++) mebj[kk] = g_Meb[kk * D2 + j];
            float bbj = sh_bb1[j];
#pragma unroll 4
            for (int mi = 0; mi < 16; mi++) {
                int m = p_mg + (mi << 2);
                float v = bbj
                        + g_Ya[(size_t)sh_src[m] * D2 + j]
                        + g_Ya[YCOFF + (size_t)sh_dst[m] * D2 + j];
                const float* dmr = sh_dm + m * 16;
#pragma unroll
                for (int kk = 0; kk < 16; kk++) v += dmr[kk] * mebj[kk];
                h1c[m * 72 + p_k] = __float2half_rn(gelu_f(v));
            }
        }
        __syncthreads();
        // phase 2: accT += w2_tile @ h1^T via fp16 mma (4 k16 steps per chunk)
#pragma unroll
        for (int ks = 0; ks < 4; ks++) {
            int KS16 = (ch << 2) + ks;
            uint4 A0 = w2p4[(MT0 * 32 + KS16) * 32 + lane];
            uint4 A1 = w2p4[(MT1 * 32 + KS16) * 32 + lane];
            int kk = ks << 4;
            unsigned b0[8], b1[8];
#pragma unroll
            for (int nt = 0; nt < 8; nt++) {
                const __half* qq = h1c + (nt * 8 + gid) * 72 + kk + 2 * ctid;
                b0[nt] = *(const unsigned*)(qq);
                b1[nt] = *(const unsigned*)(qq + 8);
            }
#pragma unroll
            for (int nt = 0; nt < 8; nt++) {
                mma_f16(acc0[nt][0], acc0[nt][1], acc0[nt][2], acc0[nt][3],
                        A0.x, A0.y, A0.z, A0.w, b0[nt], b1[nt]);
                mma_f16(acc1[nt][0], acc1[nt][1], acc1[nt][2], acc1[nt][3],
                        A1.x, A1.y, A1.z, A1.w, b0[nt], b1[nt]);
            }
        }
    }
    __syncthreads();
    {
        int r0 = warp * 32 + gid;
        int r1 = warp * 32 + 16 + gid;
        float br0 = sh_b2[r0], br0b = sh_b2[r0 + 8];
        float br1 = sh_b2[r1], br1b = sh_b2[r1 + 8];
#pragma unroll
        for (int nt = 0; nt < 8; nt++) {
            int cb = nt * 8 + 2 * ctid;
            sh_h2[r0 * 68 + cb]           = gelu_f(acc0[nt][0] + br0);
            sh_h2[r0 * 68 + cb + 1]       = gelu_f(acc0[nt][1] + br0);
            sh_h2[(r0 + 8) * 68 + cb]     = gelu_f(acc0[nt][2] + br0b);
            sh_h2[(r0 + 8) * 68 + cb + 1] = gelu_f(acc0[nt][3] + br0b);
            sh_h2[r1 * 68 + cb]           = gelu_f(acc1[nt][0] + br1);
            sh_h2[r1 * 68 + cb + 1]       = gelu_f(acc1[nt][1] + br1);
            sh_h2[(r1 + 8) * 68 + cb]     = gelu_f(acc1[nt][2] + br1b);
            sh_h2[(r1 + 8) * 68 + cb + 1] = gelu_f(acc1[nt][3] + br1b);
        }
    }
    __syncthreads();
    {
        int m = tid & 63;
        int tq = tid >> 6;
        float o[4];
#pragma unroll
        for (int qd = 0; qd < 4; qd++) o[qd] = b3[tq * 4 + qd];
        for (int i = 0; i < 256; i++) {
            float hh = sh_h2[i * 68 + m];
#pragma unroll
            for (int qd = 0; qd < 4; qd++) o[qd] += hh * sh_w3[(tq * 4 + qd) * 256 + i];
        }
        *(float4*)(dm_out + (size_t)(e0 + m) * 16 + tq * 4) =
            make_float4(o[0], o[1], o[2], o[3]);
    }
}

// ---------------- epilogue ----------------
__global__ void k_epilogue(const float* __restrict__ h0,
                           const float* __restrict__ alpha,
                           float* __restrict__ out) {
    int i = blockIdx.x * 256 + threadIdx.x;
    int n = i >> 8, d = i & 255;
    float a = alpha[0];
    const float theta = 0.69314718055994531f;
    float xo = g_cat[(size_t)n * D3 + d];
    float hg = g_cat[(size_t)n * D3 + 256 + d];
    float r = (1.f - a) * (xo + hg) + 2.f * a * h0[i];
    out[i] = g_tmp[i] + (1.f - theta) * r;
}

// ---------------- host ----------------
static float* sym_addr(const void* sym) {
    void* p = nullptr;
    cudaGetSymbolAddress(&p, sym);
    return (float*)p;
}

struct HxRes {
    cudaStream_t s2;
    cudaEvent_t ef, ej, efin;
    HxRes() {
        cudaStreamCreateWithFlags(&s2, cudaStreamNonBlocking);
        cudaEventCreateWithFlags(&ef, cudaEventDisableTiming);
        cudaEventCreateWithFlags(&ej, cudaEventDisableTiming);
        cudaEventCreateWithFlags(&efin, cudaEventDisableTiming);
    }
};

extern "C" void kernel_launch(void* const* d_in, const int* in_sizes, int n_in,
                              void* d_out, int out_size) {
    static HxRes R;

    int I_in = 0, I_adj = 1, I_h0 = 2, I_al, I_dm, I_nm, I_wl, I_wg, I_lw, I_lb,
        I_w1, I_b1, I_w2, I_b2, I_w3, I_b3, I_ipw, I_ipb, I_opw, I_opb;
    if (n_in >= 22) {
        I_al = 4; I_dm = 6; I_nm = 7; I_wl = 8; I_wg = 9; I_lw = 10; I_lb = 11;
        I_w1 = 12; I_b1 = 13; I_w2 = 14; I_b2 = 15; I_w3 = 16; I_b3 = 17;
        I_ipw = 18; I_ipb = 19; I_opw = 20; I_opb = 21;
    } else {
        I_al = 3; I_dm = 4; I_nm = 5; I_wl = 6; I_wg = 7; I_lw = 8; I_lb = 9;
        I_w1 = 10; I_b1 = 11; I_w2 = 12; I_b2 = 13; I_w3 = 14; I_b3 = 15;
        I_ipw = 16; I_ipb = 17; I_opw = 18; I_opb = 19;
    }
    const float* input = (const float*)d_in[I_in];
    const void*  adj   = d_in[I_adj];
    const float* h0    = (const float*)d_in[I_h0];
    const float* alpha = (const float*)d_in[I_al];
    const float* dmap  = (const float*)d_in[I_dm];
    const float* norm  = (const float*)d_in[I_nm];
    const float* Wl    = (const float*)d_in[I_wl];
    const float* Wg    = (const float*)d_in[I_wg];
    const float* lin_w = (const float*)d_in[I_lw];
    const float* lin_b = (const float*)d_in[I_lb];
    const float* w1    = (const float*)d_in[I_w1];
    const float* b1    = (const float*)d_in[I_b1];
    const float* w2    = (const float*)d_in[I_w2];
    const float* b2    = (const float*)d_in[I_b2];
    const float* w3    = (const float*)d_in[I_w3];
    const float* b3    = (const float*)d_in[I_b3];
    const float* ipw   = (const float*)d_in[I_ipw];
    const float* ipb   = (const float*)d_in[I_ipb];
    const float* opw   = (const float*)d_in[I_opw];
    const float* opb   = (const float*)d_in[I_opb];

    float* out    = (float*)d_out;
    float* dm_out = out + (size_t)NN * DD;

    float* cat    = sym_addr(g_cat);
    float* Ya     = sym_addr(g_Ya);
    float* qkv    = sym_addr(g_qkv);
    float* attnO  = sym_addr(g_attnO);
    float* tmp    = sym_addr(g_tmp);

    cudaFuncSetAttribute(k_edge, cudaFuncAttributeMaxDynamicSharedMemorySize,
                         SMEM_EDGE_FLOATS * 4);
    cudaFuncSetAttribute(k_flash, cudaFuncAttributeMaxDynamicSharedMemorySize,
                         SMEM_FLASH_FLOATS * 4);

    const float theta = 0.69314718055994531f;

    cudaEventRecord(R.ef, 0);
    cudaStreamWaitEvent(R.s2, R.ef, 0);

    k_detect<<<1, 32>>>(adj);
    k_init<<<8464, 256>>>(input, h0);
    k_scatter<<<16384, 256>>>(adj, input, dmap, norm);
    gemm_tc<<<dim3(6, 32), 256, 0, R.s2>>>(input, DD, ipw, DD, qkv, D3, DD, 1.f, ipb, 0, 1, 0, 0, 0);
    k_qkvh<<<3072, 256, 0, R.s2>>>();
    k_flash<<<dim3(128, 2), 256, SMEM_FLASH_FLOATS * 4, R.s2>>>();
    gemm_tc<<<dim3(2, 32), 256, 0, R.s2>>>(attnO, DD, opw, DD, cat + 256, D3, DD, 1.f, opb, 0, 1, 0, 0, 0);
    gemm_tc<<<dim3(2, 32), 256, 0, R.s2>>>(cat + 256, D3, Wg,            DD, tmp, DD, DD, theta, nullptr, 0, 0, 0, 0, 0);
    gemm_tc<<<dim3(2, 32), 256, 0, R.s2>>>(cat + 512, D3, Wl + DD * DD,  DD, tmp, DD, DD, theta, nullptr, 1, 0, 0, 0, 0);
    gemm_tc<<<dim3(2, 32), 256, 0, R.s2>>>(cat + 512, D3, Wg + DD * DD,  DD, tmp, DD, DD, theta, nullptr, 1, 0, 0, 0, 0);

    k_meb<<<16, 256>>>(lin_w, lin_b, w1, b1);
    k_w2pack<<<64, 256>>>(w2);
    k_finalize_xout<<<4096, 256>>>(lin_w, lin_b);
    cudaEventRecord(R.efin, 0);

    cudaStreamWaitEvent(R.s2, R.efin, 0);
    gemm_tc<<<dim3(2, 32), 256, 0, R.s2>>>(cat, D3, Wl, DD, tmp, DD, DD, theta, nullptr, 1, 0, 0, 0, 0);
    cudaEventRecord(R.ej, R.s2);

    gemm_tc<<<dim3(4, 32, 2), 256>>>(cat, D3, w1, D3, Ya, D2, DD, 1.f, nullptr, 0, 1, 0,
                                     512, (long)NN * D2);

    k_edge<<<2048, 256, SMEM_EDGE_FLOATS * 4>>>(adj, dmap, b2, w3, b3, dm_out);

    cudaStreamWaitEvent(0, R.ej, 0);
    k_epilogue<<<4096, 256>>>(h0, alpha, out);
}